// round 1
// baseline (speedup 1.0000x reference)
#include <cuda_runtime.h>

// Problem constants
constexpr int BATCH = 32;
constexpr int CH    = 256;    // C == D
constexpr int KCODE = 1024;   // codebook size
constexpr int HWS   = 1024;   // H*W = 32*32
constexpr int NPOS  = BATCH * HWS;        // 32768 flattened positions
constexpr long long TOT = (long long)BATCH * CH * HWS;  // 8388608 z_e elements
constexpr float BETA_W = 0.25f;

// Scratch (no allocations allowed) — zeroed/rewritten every launch.
__device__ float  g_e2[KCODE];
__device__ int    g_counts[KCODE];
__device__ int    g_idx[NPOS];
__device__ double g_partials[256];

// ---------------------------------------------------------------------------
// Kernel 1: codebook squared norms + zero the histogram / partials
// grid: 128 x 256 (1024 warps, one warp per codebook row)
// ---------------------------------------------------------------------------
__global__ void init_kernel(const float* __restrict__ embed) {
    int gid  = blockIdx.x * blockDim.x + threadIdx.x;
    int warp = gid >> 5;
    int lane = gid & 31;
    if (warp < KCODE) {
        const float* row = embed + warp * CH;
        float s = 0.f;
        #pragma unroll
        for (int i = lane; i < CH; i += 32) { float v = row[i]; s = fmaf(v, v, s); }
        #pragma unroll
        for (int o = 16; o; o >>= 1) s += __shfl_xor_sync(0xffffffffu, s, o);
        if (lane == 0) g_e2[warp] = s;
    }
    if (gid < KCODE) g_counts[gid] = 0;
    if (gid < 256)   g_partials[gid] = 0.0;
}

// ---------------------------------------------------------------------------
// Kernel 2: fused GEMM + argmin.
// Per block: 128 positions of one batch image vs all 1024 codes.
// S[k][m] = sum_c E[k][c] * Z_b[c][m];  score = e2[k] - 2*S;  argmin over k.
// grid: (HWS/128, BATCH) = (8, 32); 256 threads; 8x8 register micro-tile.
// ---------------------------------------------------------------------------
__global__ void __launch_bounds__(256) argmin_kernel(
    const float* __restrict__ z_e,
    const float* __restrict__ embed,
    float* __restrict__ out)
{
    __shared__ float Es[32][129];   // [c][k], +1 pad: conflict-free strided store
    __shared__ float Zs[32][128];   // [c][m], rows 16B-aligned for float4 reads
    __shared__ unsigned long long best[128];

    const int tid = threadIdx.x;
    const int tx  = tid & 15;   // position micro-group (8 positions)
    const int ty  = tid >> 4;   // code micro-group (8 codes)
    const int b   = blockIdx.y;
    const int m0  = blockIdx.x * 128;
    const float* zb = z_e + (size_t)b * CH * HWS;

    if (tid < 128) best[tid] = 0xFFFFFFFFFFFFFFFFull;

    for (int kt = 0; kt < KCODE; kt += 128) {
        float acc[8][8];
        #pragma unroll
        for (int i = 0; i < 8; i++)
            #pragma unroll
            for (int j = 0; j < 8; j++) acc[i][j] = 0.f;

        for (int ct = 0; ct < CH; ct += 32) {
            __syncthreads();   // protect smem reuse (prev compute / best init)
            #pragma unroll
            for (int l = 0; l < 16; l++) {
                int idx = tid + l * 256;
                int kk = idx >> 5, cc = idx & 31;                 // E: coalesced in c
                Es[cc][kk] = embed[(kt + kk) * CH + (ct + cc)];
                int mm = idx & 127, c2 = idx >> 7;                // Z: coalesced in m
                Zs[c2][mm] = zb[(size_t)(ct + c2) * HWS + m0 + mm];
            }
            __syncthreads();

            #pragma unroll
            for (int cc = 0; cc < 32; cc++) {
                float a[8], bv[8];
                #pragma unroll
                for (int i = 0; i < 8; i++) a[i] = Es[cc][ty * 8 + i]; // broadcast
                float4 b0 = *(const float4*)&Zs[cc][tx * 8];
                float4 b1 = *(const float4*)&Zs[cc][tx * 8 + 4];
                bv[0]=b0.x; bv[1]=b0.y; bv[2]=b0.z; bv[3]=b0.w;
                bv[4]=b1.x; bv[5]=b1.y; bv[6]=b1.z; bv[7]=b1.w;
                #pragma unroll
                for (int i = 0; i < 8; i++)
                    #pragma unroll
                    for (int j = 0; j < 8; j++)
                        acc[i][j] = fmaf(a[i], bv[j], acc[i][j]);
            }
        }

        // score = e2[k] - 2*dot; local argmin over this thread's 8 codes,
        // then lock-free global (per-block) argmin via ordered-uint atomicMin.
        float e2v[8];
        #pragma unroll
        for (int i = 0; i < 8; i++) e2v[i] = g_e2[kt + ty * 8 + i];

        #pragma unroll
        for (int j = 0; j < 8; j++) {
            float bv2  = e2v[0] - 2.f * acc[0][j];
            int   bk   = kt + ty * 8;
            #pragma unroll
            for (int i = 1; i < 8; i++) {
                float s = e2v[i] - 2.f * acc[i][j];
                if (s < bv2) { bv2 = s; bk = kt + ty * 8 + i; }  // strict < : first-wins
            }
            unsigned int u = __float_as_uint(bv2);
            u = (u & 0x80000000u) ? ~u : (u | 0x80000000u);      // order-preserving map
            unsigned long long packed =
                ((unsigned long long)u << 32) | (unsigned int)bk; // ties -> lower idx
            atomicMin(&best[tx * 8 + j], packed);
        }
    }

    __syncthreads();
    if (tid < 128) {
        int code = (int)(best[tid] & 0xFFFFFFFFull);
        int n = b * HWS + m0 + tid;
        g_idx[n] = code;
        out[TOT + n] = (float)code;          // indices output (as float)
        atomicAdd(&g_counts[code], 1);       // usage histogram (int: deterministic)
    }
}

// ---------------------------------------------------------------------------
// Kernel 3: write z_q_st (== z_q forward value) in (B,C,H,W) layout,
// accumulate commitment-loss partial per block (deterministic slots).
// grid: 256 x 256
// ---------------------------------------------------------------------------
__global__ void __launch_bounds__(256) zq_kernel(
    const float* __restrict__ z_e,
    const float* __restrict__ embed,
    float* __restrict__ out)
{
    __shared__ double sred[256];
    const int tid = threadIdx.x;
    long long gid    = (long long)blockIdx.x * blockDim.x + tid;
    long long stride = (long long)gridDim.x * blockDim.x;

    float loc = 0.f;
    for (long long e = gid; e < TOT; e += stride) {
        int m = (int)(e & (HWS - 1));
        int c = (int)((e >> 10) & (CH - 1));
        int b = (int)(e >> 18);
        int idx = g_idx[(b << 10) + m];
        float q = embed[idx * CH + c];
        out[e] = q;
        float d = z_e[e] - q;
        loc = fmaf(d, d, loc);
    }
    sred[tid] = (double)loc;
    __syncthreads();
    for (int o = 128; o; o >>= 1) {
        if (tid < o) sred[tid] += sred[tid + o];
        __syncthreads();
    }
    if (tid == 0) g_partials[blockIdx.x] = sred[0];
}

// ---------------------------------------------------------------------------
// Kernel 4: scalars — vq_loss and perplexity. 1 block x 1024 threads.
// ---------------------------------------------------------------------------
__global__ void finalize_kernel(float* __restrict__ out) {
    __shared__ double sh[1024];
    const int tid = threadIdx.x;
    float p = (float)g_counts[tid] / (float)NPOS;
    sh[tid] = (double)(p * logf(p + 1e-10f));
    __syncthreads();
    for (int o = 512; o; o >>= 1) {
        if (tid < o) sh[tid] += sh[tid + o];
        __syncthreads();
    }
    if (tid == 0) {
        double ent = sh[0];
        double ls = 0.0;
        for (int i = 0; i < 256; i++) ls += g_partials[i];   // fixed order: deterministic
        out[TOT + NPOS]     = BETA_W * (float)(ls / (double)TOT);
        out[TOT + NPOS + 1] = expf(-(float)ent);
    }
}

// ---------------------------------------------------------------------------
extern "C" void kernel_launch(void* const* d_in, const int* in_sizes, int n_in,
                              void* d_out, int out_size) {
    const float* z_e   = (const float*)d_in[0];   // (32,256,32,32) f32
    const float* embed = (const float*)d_in[1];   // (1024,256)     f32
    float* out = (float*)d_out;

    init_kernel<<<128, 256>>>(embed);
    dim3 grid(HWS / 128, BATCH);
    argmin_kernel<<<grid, 256>>>(z_e, embed, out);
    zq_kernel<<<256, 256>>>(z_e, embed, out);
    finalize_kernel<<<1, 1024>>>(out);
}

// round 2
// speedup vs baseline: 1.0974x; 1.0974x over previous
#include <cuda_runtime.h>

// Problem constants
constexpr int BATCH = 32;
constexpr int CH    = 256;    // C == D
constexpr int KCODE = 1024;   // codebook size
constexpr int HWS   = 1024;   // H*W = 32*32
constexpr int NPOS  = BATCH * HWS;        // 32768 flattened positions
constexpr long long TOT = (long long)BATCH * CH * HWS;  // 8388608 z_e elements
constexpr float BETA_W = 0.25f;

typedef unsigned long long ull;

// Packed f32x2 helpers (sm_100+; ptxas never auto-fuses — PTX only)
__device__ __forceinline__ void fma2(ull& d, ull a, ull b, ull c) {
    asm("fma.rn.f32x2 %0, %1, %2, %3;" : "=l"(d) : "l"(a), "l"(b), "l"(c));
}
__device__ __forceinline__ ull pack2(float x, float y) {
    ull r; asm("mov.b64 %0, {%1, %2};" : "=l"(r) : "f"(x), "f"(y)); return r;
}
__device__ __forceinline__ void unpack2(float& x, float& y, ull v) {
    asm("mov.b64 {%0, %1}, %2;" : "=f"(x), "=f"(y) : "l"(v));
}

// Scratch (no allocations allowed) — zeroed/rewritten every launch.
__device__ float  g_e2[KCODE];
__device__ int    g_counts[KCODE];
__device__ int    g_idx[NPOS];
__device__ double g_partials[256];

// ---------------------------------------------------------------------------
// Kernel 1: codebook squared norms + zero the histogram / partials
// ---------------------------------------------------------------------------
__global__ void init_kernel(const float* __restrict__ embed) {
    int gid  = blockIdx.x * blockDim.x + threadIdx.x;
    int warp = gid >> 5;
    int lane = gid & 31;
    if (warp < KCODE) {
        const float* row = embed + warp * CH;
        float s = 0.f;
        #pragma unroll
        for (int i = lane; i < CH; i += 32) { float v = row[i]; s = fmaf(v, v, s); }
        #pragma unroll
        for (int o = 16; o; o >>= 1) s += __shfl_xor_sync(0xffffffffu, s, o);
        if (lane == 0) g_e2[warp] = s;
    }
    if (gid < KCODE) g_counts[gid] = 0;
    if (gid < 256)   g_partials[gid] = 0.0;
}

// ---------------------------------------------------------------------------
// Kernel 2: fused GEMM + argmin, FFMA2 (packed f32x2) inner loop.
// Per block: 128 positions of one batch image vs all 1024 codes.
// S[k][m] = sum_c E[k][c] * Z_b[c][m];  score = e2[k] - 2*S;  argmin over k.
// grid: (HWS/128, BATCH) = (8, 32); 256 threads; 8x8 register micro-tile,
// accumulators packed in pairs along the position axis (j).
// ---------------------------------------------------------------------------
__global__ void __launch_bounds__(256) argmin_kernel(
    const float* __restrict__ z_e,
    const float* __restrict__ embed,
    float* __restrict__ out)
{
    __shared__ float Es[32][129];   // [c][k], +1 pad: conflict-free strided store
    __shared__ float Zs[32][128];   // [c][m], rows 16B-aligned for vector reads
    __shared__ unsigned long long best[128];

    const int tid = threadIdx.x;
    const int tx  = tid & 15;   // position micro-group (8 positions = 4 pairs)
    const int ty  = tid >> 4;   // code micro-group (8 codes)
    const int b   = blockIdx.y;
    const int m0  = blockIdx.x * 128;
    const float* zb = z_e + (size_t)b * CH * HWS;

    if (tid < 128) best[tid] = 0xFFFFFFFFFFFFFFFFull;

    for (int kt = 0; kt < KCODE; kt += 128) {
        ull acc2[8][4];
        #pragma unroll
        for (int i = 0; i < 8; i++)
            #pragma unroll
            for (int jp = 0; jp < 4; jp++) acc2[i][jp] = 0ull;  // two packed +0.f

        for (int ct = 0; ct < CH; ct += 32) {
            __syncthreads();   // protect smem reuse (prev compute / best init)
            #pragma unroll
            for (int l = 0; l < 16; l++) {
                int idx = tid + l * 256;
                int kk = idx >> 5, cc = idx & 31;                 // E: coalesced in c
                Es[cc][kk] = embed[(kt + kk) * CH + (ct + cc)];
                int mm = idx & 127, c2 = idx >> 7;                // Z: coalesced in m
                Zs[c2][mm] = zb[(size_t)(ct + c2) * HWS + m0 + mm];
            }
            __syncthreads();

            #pragma unroll
            for (int cc = 0; cc < 32; cc++) {
                ull a2[8];
                #pragma unroll
                for (int i = 0; i < 8; i++) {
                    float a = Es[cc][ty * 8 + i];                 // broadcast LDS
                    a2[i] = pack2(a, a);
                }
                // 8 consecutive positions = 4 packed pairs (LDS.128 x2)
                ulonglong2 bA = *(const ulonglong2*)&Zs[cc][tx * 8];
                ulonglong2 bB = *(const ulonglong2*)&Zs[cc][tx * 8 + 4];
                ull b2[4] = {bA.x, bA.y, bB.x, bB.y};
                #pragma unroll
                for (int i = 0; i < 8; i++)
                    #pragma unroll
                    for (int jp = 0; jp < 4; jp++)
                        fma2(acc2[i][jp], a2[i], b2[jp], acc2[i][jp]);
            }
        }

        // score = e2[k] - 2*dot; local argmin over this thread's 8 codes,
        // then lock-free per-block argmin via ordered-uint atomicMin.
        float e2v[8];
        #pragma unroll
        for (int i = 0; i < 8; i++) e2v[i] = g_e2[kt + ty * 8 + i];

        #pragma unroll
        for (int jp = 0; jp < 4; jp++) {
            float s0[8], s1[8];
            #pragma unroll
            for (int i = 0; i < 8; i++) {
                float lo, hi; unpack2(lo, hi, acc2[i][jp]);
                s0[i] = e2v[i] - 2.f * lo;
                s1[i] = e2v[i] - 2.f * hi;
            }
            #pragma unroll
            for (int half = 0; half < 2; half++) {
                const float* s = half ? s1 : s0;
                float bv2 = s[0];
                int   bk  = kt + ty * 8;
                #pragma unroll
                for (int i = 1; i < 8; i++) {
                    if (s[i] < bv2) { bv2 = s[i]; bk = kt + ty * 8 + i; } // first-wins
                }
                unsigned int u = __float_as_uint(bv2);
                u = (u & 0x80000000u) ? ~u : (u | 0x80000000u);  // order-preserving map
                unsigned long long packed =
                    ((unsigned long long)u << 32) | (unsigned int)bk; // ties -> lower idx
                atomicMin(&best[tx * 8 + jp * 2 + half], packed);
            }
        }
    }

    __syncthreads();
    if (tid < 128) {
        int code = (int)(best[tid] & 0xFFFFFFFFull);
        int n = b * HWS + m0 + tid;
        g_idx[n] = code;
        out[TOT + n] = (float)code;          // indices output (as float)
        atomicAdd(&g_counts[code], 1);       // usage histogram (int: deterministic)
    }
}

// ---------------------------------------------------------------------------
// Kernel 3: write z_q_st (== z_q forward value) in (B,C,H,W) layout,
// accumulate commitment-loss partial per block (deterministic slots).
// ---------------------------------------------------------------------------
__global__ void __launch_bounds__(256) zq_kernel(
    const float* __restrict__ z_e,
    const float* __restrict__ embed,
    float* __restrict__ out)
{
    __shared__ double sred[256];
    const int tid = threadIdx.x;
    long long gid    = (long long)blockIdx.x * blockDim.x + tid;
    long long stride = (long long)gridDim.x * blockDim.x;

    float loc = 0.f;
    for (long long e = gid; e < TOT; e += stride) {
        int m = (int)(e & (HWS - 1));
        int c = (int)((e >> 10) & (CH - 1));
        int b = (int)(e >> 18);
        int idx = g_idx[(b << 10) + m];
        float q = embed[idx * CH + c];
        out[e] = q;
        float d = z_e[e] - q;
        loc = fmaf(d, d, loc);
    }
    sred[tid] = (double)loc;
    __syncthreads();
    for (int o = 128; o; o >>= 1) {
        if (tid < o) sred[tid] += sred[tid + o];
        __syncthreads();
    }
    if (tid == 0) g_partials[blockIdx.x] = sred[0];
}

// ---------------------------------------------------------------------------
// Kernel 4: scalars — vq_loss and perplexity. 1 block x 1024 threads.
// Loss partials reduced with a parallel tree (deterministic order), not a
// 256-long serial DADD chain.
// ---------------------------------------------------------------------------
__global__ void finalize_kernel(float* __restrict__ out) {
    __shared__ double sh[1024];
    __shared__ double sl[256];
    const int tid = threadIdx.x;

    float p = (float)g_counts[tid] / (float)NPOS;
    sh[tid] = (double)(p * logf(p + 1e-10f));
    if (tid < 256) sl[tid] = g_partials[tid];
    __syncthreads();
    for (int o = 512; o; o >>= 1) {
        if (tid < o) sh[tid] += sh[tid + o];
        if (o <= 128 && tid < o) sl[tid] += sl[tid + o];
        __syncthreads();
    }
    if (tid == 0) {
        out[TOT + NPOS]     = BETA_W * (float)(sl[0] / (double)TOT);
        out[TOT + NPOS + 1] = expf(-(float)sh[0]);
    }
}

// ---------------------------------------------------------------------------
extern "C" void kernel_launch(void* const* d_in, const int* in_sizes, int n_in,
                              void* d_out, int out_size) {
    const float* z_e   = (const float*)d_in[0];   // (32,256,32,32) f32
    const float* embed = (const float*)d_in[1];   // (1024,256)     f32
    float* out = (float*)d_out;

    init_kernel<<<128, 256>>>(embed);
    dim3 grid(HWS / 128, BATCH);
    argmin_kernel<<<grid, 256>>>(z_e, embed, out);
    zq_kernel<<<256, 256>>>(z_e, embed, out);
    finalize_kernel<<<1, 1024>>>(out);
}

// round 4
// speedup vs baseline: 1.3542x; 1.2340x over previous
#include <cuda_runtime.h>
#include <cuda_bf16.h>
#include <cstdint>

// ───────────────────────── problem constants ─────────────────────────
constexpr int BATCH = 32;
constexpr int CH    = 256;     // C == D == K(gemm)
constexpr int KCODE = 1024;    // codebook size
constexpr int HWS   = 1024;    // H*W
constexpr int NPOS  = BATCH * HWS;                 // 32768 positions
constexpr long long TOT = (long long)NPOS * CH;    // 8388608 z_e elements
constexpr float BETA_W = 0.25f;
constexpr float MARGIN = 0.02f;   // >>10x the split-bf16 error bound (~1e-3)

// smem layout (bytes)
constexpr int SB_A   = 0;                 // A_hi: 256 rows x 512B (swizzled)   = 131072
constexpr int SB_AL0 = 131072;            // A_lo slab buf0: 256 rows x 128B    = 32768
constexpr int SB_AL1 = 163840;            // A_lo slab buf1                     = 32768
constexpr int SB_B   = 196608;            // B plane: 64 rows x 512B            = 32768
constexpr int SMEM_TOTAL = 229376;        // 224KB (max dynamic 227KB)

// ───────────────────────── device scratch ─────────────────────────
__device__ __align__(16) __nv_bfloat16 g_Zh[(size_t)NPOS * CH];  // [n][c]
__device__ __align__(16) __nv_bfloat16 g_Zl[(size_t)NPOS * CH];
__device__ __align__(16) __nv_bfloat16 g_Eh[(size_t)KCODE * CH]; // [k][c]
__device__ __align__(16) __nv_bfloat16 g_El[(size_t)KCODE * CH];
__device__ float  g_e2[KCODE];
__device__ int    g_counts[KCODE];
__device__ int    g_idx[NPOS];
__device__ double g_partials[256];
__device__ int    g_nflag;
__device__ int    g_flag[NPOS];

// ───────────────────────── PTX helpers ─────────────────────────
__device__ __forceinline__ uint32_t smem_u32(const void* p) {
    uint32_t a;
    asm("{ .reg .u64 t; cvta.to.shared.u64 t, %1; cvt.u32.u64 %0, t; }" : "=r"(a) : "l"(p));
    return a;
}
__device__ __forceinline__ void cp16(uint32_t dst, const void* src) {
    asm volatile("cp.async.cg.shared.global [%0], [%1], 16;" :: "r"(dst), "l"(src));
}
#define CP_COMMIT() asm volatile("cp.async.commit_group;" ::: "memory")
#define CP_WAIT0()  asm volatile("cp.async.wait_group 0;" ::: "memory")
#define CP_WAIT1()  asm volatile("cp.async.wait_group 1;" ::: "memory")

__device__ __forceinline__ void ldsm_x4(uint32_t& r0, uint32_t& r1, uint32_t& r2,
                                        uint32_t& r3, uint32_t addr) {
    asm volatile("ldmatrix.sync.aligned.m8n8.x4.shared.b16 {%0,%1,%2,%3}, [%4];"
                 : "=r"(r0), "=r"(r1), "=r"(r2), "=r"(r3) : "r"(addr));
}
__device__ __forceinline__ void mma16816(float* d, const uint32_t* a, uint32_t b0, uint32_t b1) {
    asm volatile("mma.sync.aligned.m16n8k16.row.col.f32.bf16.bf16.f32 "
                 "{%0,%1,%2,%3}, {%4,%5,%6,%7}, {%8,%9}, {%0,%1,%2,%3};"
                 : "+f"(d[0]), "+f"(d[1]), "+f"(d[2]), "+f"(d[3])
                 : "r"(a[0]), "r"(a[1]), "r"(a[2]), "r"(a[3]), "r"(b0), "r"(b1));
}
__device__ __forceinline__ unsigned ordmap(float f) {
    unsigned u = __float_as_uint(f);
    return (u & 0x80000000u) ? ~u : (u | 0x80000000u);
}
__device__ __forceinline__ float unord(unsigned v) {
    v = (v & 0x80000000u) ? (v & 0x7FFFFFFFu) : ~v;
    return __uint_as_float(v);
}

// ───────────────────────── kernel 1: e2 + zero scratch ─────────────────────────
__global__ void init_kernel(const float* __restrict__ embed) {
    int gid = blockIdx.x * blockDim.x + threadIdx.x;
    int warp = gid >> 5, lane = gid & 31;
    if (warp < KCODE) {
        const float* row = embed + warp * CH;
        float s = 0.f;
        #pragma unroll
        for (int i = lane; i < CH; i += 32) { float v = row[i]; s = fmaf(v, v, s); }
        #pragma unroll
        for (int o = 16; o; o >>= 1) s += __shfl_xor_sync(0xffffffffu, s, o);
        if (lane == 0) g_e2[warp] = s;
    }
    if (gid < KCODE) g_counts[gid] = 0;
    if (gid < 256)   g_partials[gid] = 0.0;
    if (gid == 0)    g_nflag = 0;
}

// ───────────────────────── kernel 2: split-bf16 codebook ─────────────────────────
__global__ void convert_e_kernel(const float* __restrict__ embed) {
    int base = blockIdx.x * blockDim.x + threadIdx.x;
    for (int i = base; i < KCODE * CH; i += gridDim.x * blockDim.x) {
        float v = embed[i];
        __nv_bfloat16 hi = __float2bfloat16(v);
        __nv_bfloat16 lo = __float2bfloat16(v - __bfloat162float(hi));
        g_Eh[i] = hi; g_El[i] = lo;
    }
}

// ───────────────────────── kernel 3: transpose+split z_e → [n][c] bf16 ────────────
__global__ void convert_z_kernel(const float* __restrict__ z_e) {
    __shared__ float T[32][33];
    int tx = threadIdx.x, ty = threadIdx.y;          // block (32,8)
    int m0 = blockIdx.x * 32, c0 = blockIdx.y * 32, b = blockIdx.z;
    #pragma unroll
    for (int i = 0; i < 4; i++) {
        int c = ty + i * 8;
        T[c][tx] = z_e[((size_t)b * CH + c0 + c) * HWS + m0 + tx];   // coalesced in m
    }
    __syncthreads();
    #pragma unroll
    for (int i = 0; i < 4; i++) {
        int r = ty + i * 8;                                           // m_local
        float v = T[tx][r];                                           // tx = c_local
        size_t o = (size_t)(b * HWS + m0 + r) * CH + c0 + tx;         // coalesced in c
        __nv_bfloat16 hi = __float2bfloat16(v);
        __nv_bfloat16 lo = __float2bfloat16(v - __bfloat162float(hi));
        g_Zh[o] = hi; g_Zl[o] = lo;
    }
}

// ───────────────────────── kernel 4: HMMA GEMM + argmin ─────────────────────────
// CTA = 256 positions vs all 1024 codes in 16 chunks of 64.
// Per chunk, K_eff = 768: seg0 xh*eh, seg2 xl*eh (A_lo slabs pipelined), seg1 xh*el.
// Warp tile M32 x N64: each warp sees ALL codes for its 32 rows.
__global__ void __launch_bounds__(256, 1) mma_argmin_kernel(float* __restrict__ out) {
    extern __shared__ char smem[];
    const uint32_t sb = smem_u32(smem);
    const int tid = threadIdx.x;
    const int lane = tid & 31, wid = tid >> 5;
    const int mrow = wid * 32;
    const int n0 = blockIdx.x * 256;

    // A_hi resident load: 256 rows x 32 x 16B, coalesced
    #pragma unroll
    for (int it = 0; it < 32; it++) {
        int u = tid + it * 256;
        int row = u >> 5, cu = u & 31;
        cp16(sb + SB_A + row * 512 + ((cu * 16) ^ ((row & 7) << 4)),
             g_Zh + (size_t)(n0 + row) * 256 + cu * 8);
    }
    CP_COMMIT();

    unsigned long long bs[4], ss[4];
    #pragma unroll
    for (int si = 0; si < 4; si++) { bs[si] = ~0ull; ss[si] = ~0ull; }

    float acc[2][8][4];

    const uint32_t albuf[2] = { sb + SB_AL0, sb + SB_AL1 };

    for (int chunk = 0; chunk < 16; chunk++) {
        // ---- load B = Eh[chunk] (waits also drain A_hi on first chunk) ----
        __syncthreads();
        #pragma unroll
        for (int it = 0; it < 8; it++) {
            int u = tid + it * 256;
            int row = u >> 5, cu = u & 31;
            cp16(sb + SB_B + row * 512 + ((cu * 16) ^ ((row & 7) << 4)),
                 g_Eh + (size_t)(chunk * 64 + row) * 256 + cu * 8);
        }
        CP_COMMIT();
        CP_WAIT0();
        __syncthreads();

        // prefetch A_lo slab 0 (k 0..63) into buf0
        #pragma unroll
        for (int it = 0; it < 8; it++) {
            int u = tid + it * 256;
            int row = u >> 3, cu = u & 7;
            cp16(albuf[0] + row * 128 + ((cu * 16) ^ ((row & 7) << 4)),
                 g_Zl + (size_t)(n0 + row) * 256 + cu * 8);
        }
        CP_COMMIT();

        #pragma unroll
        for (int mt = 0; mt < 2; mt++)
            #pragma unroll
            for (int nt = 0; nt < 8; nt++)
                #pragma unroll
                for (int e = 0; e < 4; e++) acc[mt][nt][e] = 0.f;

        // ---- seg0: A_hi x Eh, K = 256 (16 ksteps) ----
        #pragma unroll
        for (int ks = 0; ks < 16; ks++) {
            uint32_t a[2][4];
            #pragma unroll
            for (int mt = 0; mt < 2; mt++) {
                int row = mrow + mt * 16 + (lane & 15);
                int colb = ks * 32 + ((lane >> 4) << 4);
                ldsm_x4(a[mt][0], a[mt][1], a[mt][2], a[mt][3],
                        sb + SB_A + row * 512 + (colb ^ ((row & 7) << 4)));
            }
            uint32_t bq[4][4];
            #pragma unroll
            for (int p = 0; p < 4; p++) {
                int row = p * 16 + (lane & 7) + ((lane >> 4) << 3);
                int colb = ks * 32 + ((lane & 8) << 1);
                ldsm_x4(bq[p][0], bq[p][1], bq[p][2], bq[p][3],
                        sb + SB_B + row * 512 + (colb ^ ((row & 7) << 4)));
            }
            #pragma unroll
            for (int mt = 0; mt < 2; mt++)
                #pragma unroll
                for (int nt = 0; nt < 8; nt++)
                    mma16816(acc[mt][nt], a[mt], bq[nt >> 1][(nt & 1) * 2],
                             bq[nt >> 1][(nt & 1) * 2 + 1]);
        }

        // ---- seg2: A_lo x Eh, K = 256, 4 slabs of 64, double-buffered ----
        #pragma unroll 1
        for (int s = 0; s < 4; s++) {
            __syncthreads();                 // all warps done with buf (s+1)&1
            if (s < 3) {
                #pragma unroll
                for (int it = 0; it < 8; it++) {
                    int u = tid + it * 256;
                    int row = u >> 3, cu = u & 7;
                    cp16(albuf[(s + 1) & 1] + row * 128 + ((cu * 16) ^ ((row & 7) << 4)),
                         g_Zl + (size_t)(n0 + row) * 256 + (s + 1) * 64 + cu * 8);
                }
                CP_COMMIT();
                CP_WAIT1();                  // slab s done, s+1 in flight
            } else {
                CP_WAIT0();
            }
            __syncthreads();

            const uint32_t ab = albuf[s & 1];
            #pragma unroll
            for (int k = 0; k < 4; k++) {
                int ks = s * 4 + k;          // global kstep for B column
                uint32_t a[2][4];
                #pragma unroll
                for (int mt = 0; mt < 2; mt++) {
                    int row = mrow + mt * 16 + (lane & 15);
                    int colb = k * 32 + ((lane >> 4) << 4);
                    ldsm_x4(a[mt][0], a[mt][1], a[mt][2], a[mt][3],
                            ab + row * 128 + (colb ^ ((row & 7) << 4)));
                }
                uint32_t bq[4][4];
                #pragma unroll
                for (int p = 0; p < 4; p++) {
                    int row = p * 16 + (lane & 7) + ((lane >> 4) << 3);
                    int colb = ks * 32 + ((lane & 8) << 1);
                    ldsm_x4(bq[p][0], bq[p][1], bq[p][2], bq[p][3],
                            sb + SB_B + row * 512 + (colb ^ ((row & 7) << 4)));
                }
                #pragma unroll
                for (int mt = 0; mt < 2; mt++)
                    #pragma unroll
                    for (int nt = 0; nt < 8; nt++)
                        mma16816(acc[mt][nt], a[mt], bq[nt >> 1][(nt & 1) * 2],
                                 bq[nt >> 1][(nt & 1) * 2 + 1]);
            }
        }

        // ---- load B = El[chunk], then seg1: A_hi x El, K = 256 ----
        __syncthreads();
        #pragma unroll
        for (int it = 0; it < 8; it++) {
            int u = tid + it * 256;
            int row = u >> 5, cu = u & 31;
            cp16(sb + SB_B + row * 512 + ((cu * 16) ^ ((row & 7) << 4)),
                 g_El + (size_t)(chunk * 64 + row) * 256 + cu * 8);
        }
        CP_COMMIT();
        CP_WAIT0();
        __syncthreads();

        #pragma unroll
        for (int ks = 0; ks < 16; ks++) {
            uint32_t a[2][4];
            #pragma unroll
            for (int mt = 0; mt < 2; mt++) {
                int row = mrow + mt * 16 + (lane & 15);
                int colb = ks * 32 + ((lane >> 4) << 4);
                ldsm_x4(a[mt][0], a[mt][1], a[mt][2], a[mt][3],
                        sb + SB_A + row * 512 + (colb ^ ((row & 7) << 4)));
            }
            uint32_t bq[4][4];
            #pragma unroll
            for (int p = 0; p < 4; p++) {
                int row = p * 16 + (lane & 7) + ((lane >> 4) << 3);
                int colb = ks * 32 + ((lane & 8) << 1);
                ldsm_x4(bq[p][0], bq[p][1], bq[p][2], bq[p][3],
                        sb + SB_B + row * 512 + (colb ^ ((row & 7) << 4)));
            }
            #pragma unroll
            for (int mt = 0; mt < 2; mt++)
                #pragma unroll
                for (int nt = 0; nt < 8; nt++)
                    mma16816(acc[mt][nt], a[mt], bq[nt >> 1][(nt & 1) * 2],
                             bq[nt >> 1][(nt & 1) * 2 + 1]);
        }

        // ---- epilogue: dist = e2 - 2S, update running best/second ----
        const int cb = chunk * 64;
        #pragma unroll
        for (int mt = 0; mt < 2; mt++)
            #pragma unroll
            for (int nt = 0; nt < 8; nt++)
                #pragma unroll
                for (int e = 0; e < 4; e++) {
                    int code = cb + nt * 8 + (lane & 3) * 2 + (e & 1);
                    float dist = __ldg(&g_e2[code]) - 2.0f * acc[mt][nt][e];
                    unsigned long long cand =
                        ((unsigned long long)ordmap(dist) << 32) | (unsigned)code;
                    int si = mt * 2 + (e >> 1);
                    if (cand < bs[si]) { ss[si] = bs[si]; bs[si] = cand; }
                    else if (cand < ss[si]) ss[si] = cand;
                }
    }

    // ---- quad merge (lanes sharing a row) + writeout ----
    #pragma unroll
    for (int si = 0; si < 4; si++) {
        unsigned long long b = bs[si], s = ss[si];
        #pragma unroll
        for (int m = 1; m <= 2; m <<= 1) {
            unsigned long long ob = __shfl_xor_sync(0xffffffffu, b, m);
            unsigned long long os = __shfl_xor_sync(0xffffffffu, s, m);
            unsigned long long nb = b < ob ? b : ob;
            unsigned long long mx = b < ob ? ob : b;
            unsigned long long ms = s < os ? s : os;
            b = nb; s = mx < ms ? mx : ms;
        }
        if ((lane & 3) == 0) {
            int row = mrow + (si >> 1) * 16 + (lane >> 2) + (si & 1) * 8;
            int pos = n0 + row;
            int code = (int)(unsigned)(b & 0xFFFFFFFFull);
            g_idx[pos] = code;
            out[TOT + pos] = (float)code;
            atomicAdd(&g_counts[code], 1);
            float fb = unord((unsigned)(b >> 32));
            float fs = unord((unsigned)(s >> 32));
            if (fs - fb < MARGIN) {
                int sl = atomicAdd(&g_nflag, 1);
                g_flag[sl] = pos;
            }
        }
    }
}

// ───────────────────────── kernel 5: exact fp32 repair of near-ties ───────────────
__global__ void __launch_bounds__(256) repair_kernel(
    const float* __restrict__ z_e, const float* __restrict__ embed, float* __restrict__ out) {
    __shared__ float xs[256];
    __shared__ unsigned long long best;
    const int nf = g_nflag;
    for (int f = blockIdx.x; f < nf; f += gridDim.x) {
        const int pos = g_flag[f];
        const int b = pos >> 10, m = pos & (HWS - 1);
        xs[threadIdx.x] = z_e[((size_t)b * CH + threadIdx.x) * HWS + m];
        if (threadIdx.x == 0) best = ~0ull;
        __syncthreads();
        for (int k = threadIdx.x; k < KCODE; k += 256) {
            const float* er = embed + (size_t)k * CH;
            float dot = 0.f;
            #pragma unroll 8
            for (int c = 0; c < CH; c++) dot = fmaf(xs[c], er[c], dot);
            float d = g_e2[k] - 2.f * dot;
            atomicMin(&best, ((unsigned long long)ordmap(d) << 32) | (unsigned)k);
        }
        __syncthreads();
        if (threadIdx.x == 0) {
            int nk = (int)(best & 0xFFFFFFFFull), ok = g_idx[pos];
            if (nk != ok) {
                g_idx[pos] = nk;
                out[TOT + pos] = (float)nk;
                atomicAdd(&g_counts[nk], 1);
                atomicAdd(&g_counts[ok], -1);
            }
        }
        __syncthreads();
    }
}

// ───────────────────────── kernel 6: z_q gather + commitment loss ─────────────────
__global__ void __launch_bounds__(256) zq_kernel(
    const float* __restrict__ z_e, const float* __restrict__ embed, float* __restrict__ out) {
    __shared__ double sred[256];
    const int tid = threadIdx.x;
    long long gid = (long long)blockIdx.x * blockDim.x + tid;
    long long stride = (long long)gridDim.x * blockDim.x;
    float loc = 0.f;
    for (long long e = gid; e < TOT; e += stride) {
        int m = (int)(e & (HWS - 1));
        int c = (int)((e >> 10) & (CH - 1));
        int b = (int)(e >> 18);
        int idx = g_idx[(b << 10) + m];
        float q = embed[idx * CH + c];
        out[e] = q;
        float d = z_e[e] - q;
        loc = fmaf(d, d, loc);
    }
    sred[tid] = (double)loc;
    __syncthreads();
    for (int o = 128; o; o >>= 1) {
        if (tid < o) sred[tid] += sred[tid + o];
        __syncthreads();
    }
    if (tid == 0) g_partials[blockIdx.x] = sred[0];
}

// ───────────────────────── kernel 7: scalars ─────────────────────────
__global__ void finalize_kernel(float* __restrict__ out) {
    __shared__ double sh[1024];
    __shared__ double sl[256];
    const int tid = threadIdx.x;
    float p = (float)g_counts[tid] / (float)NPOS;
    sh[tid] = (double)(p * logf(p + 1e-10f));
    if (tid < 256) sl[tid] = g_partials[tid];
    __syncthreads();
    for (int o = 512; o; o >>= 1) {
        if (tid < o) sh[tid] += sh[tid + o];
        if (o <= 128 && tid < o) sl[tid] += sl[tid + o];
        __syncthreads();
    }
    if (tid == 0) {
        out[TOT + NPOS]     = BETA_W * (float)(sl[0] / (double)TOT);
        out[TOT + NPOS + 1] = expf(-(float)sh[0]);
    }
}

// ───────────────────────── host ─────────────────────────
extern "C" void kernel_launch(void* const* d_in, const int* in_sizes, int n_in,
                              void* d_out, int out_size) {
    const float* z_e   = (const float*)d_in[0];   // (32,256,32,32) f32
    const float* embed = (const float*)d_in[1];   // (1024,256)     f32
    float* out = (float*)d_out;

    cudaFuncSetAttribute(mma_argmin_kernel,
                         cudaFuncAttributeMaxDynamicSharedMemorySize, SMEM_TOTAL);

    init_kernel<<<128, 256>>>(embed);
    convert_e_kernel<<<256, 256>>>(embed);
    convert_z_kernel<<<dim3(HWS / 32, CH / 32, BATCH), dim3(32, 8)>>>(z_e);
    mma_argmin_kernel<<<NPOS / 256, 256, SMEM_TOTAL>>>(out);
    repair_kernel<<<128, 256>>>(z_e, embed, out);
    zq_kernel<<<256, 256>>>(z_e, embed, out);
    finalize_kernel<<<1, 1024>>>(out);
}